// round 1
// baseline (speedup 1.0000x reference)
#include <cuda_runtime.h>
#include <cuda_bf16.h>
#include <math.h>

#define NN 8192
#define DD 128
#define BM 64
#define BK 64
#define NBLK 128   // 8192/64

__device__ double g_sumDW;
__device__ double g_sumW;
__device__ int    g_maxSq;     // float bits, all values >= 0 -> int compare OK
__device__ float  g_norms[NN];

// ---------- packed f32x2 helpers (Blackwell FFMA2) ----------
__device__ __forceinline__ unsigned long long pk2(float lo, float hi) {
    unsigned long long r;
    asm("mov.b64 %0, {%1, %2};" : "=l"(r) : "f"(lo), "f"(hi));
    return r;
}
__device__ __forceinline__ void unpk2(unsigned long long v, float& lo, float& hi) {
    asm("mov.b64 {%0, %1}, %2;" : "=f"(lo), "=f"(hi) : "l"(v));
}
__device__ __forceinline__ void ffma2(unsigned long long& d,
                                      unsigned long long a,
                                      unsigned long long b) {
    asm("fma.rn.f32x2 %0, %1, %2, %0;" : "+l"(d) : "l"(a), "l"(b));
}

// ---------- kernel 0: init accumulators ----------
__global__ void init_kernel() {
    g_sumDW = 0.0;
    g_sumW  = 0.0;
    g_maxSq = 0;
}

// ---------- kernel 1: row squared norms ----------
__global__ __launch_bounds__(256) void norm_kernel(const float* __restrict__ emb) {
    int row = blockIdx.x * 256 + threadIdx.x;
    const float4* p = reinterpret_cast<const float4*>(emb) + (size_t)row * (DD / 4);
    float s = 0.f;
#pragma unroll
    for (int i = 0; i < DD / 4; i++) {
        float4 v = p[i];
        s += v.x * v.x + v.y * v.y + v.z * v.z + v.w * v.w;
    }
    g_norms[row] = s;
}

// ---------- kernel 2: fused GEMM + dist + weighted reductions ----------
__global__ __launch_bounds__(256) void main_kernel(const float* __restrict__ emb,
                                                   const float* __restrict__ W) {
    const int bi = blockIdx.y;
    const int bj = blockIdx.x;
    if (bj < bi) return;  // upper triangle only (dist is symmetric)

    __shared__ float sh[2 * BK * BM];  // A chunk | B chunk; later overlaid by dist[64][65]
    __shared__ float nI[BM];
    __shared__ float nJ[BM];
    __shared__ double red[256];
    __shared__ float  redf[256];

    float* As = sh;
    float* Bs = sh + BK * BM;

    const int tid = threadIdx.x;
    const int tx = tid & 15;   // j-quad 0..15
    const int ty = tid >> 4;   // i-quad 0..15
    const int gi0 = bi * BM;
    const int gj0 = bj * BM;

    if (tid < 64)       nI[tid]      = g_norms[gi0 + tid];
    else if (tid < 128) nJ[tid - 64] = g_norms[gj0 + tid - 64];

    unsigned long long acc[4][2];
#pragma unroll
    for (int ii = 0; ii < 4; ii++) {
        acc[ii][0] = 0ull;  // bits of (0.f, 0.f)
        acc[ii][1] = 0ull;
    }

    const float4* ev = reinterpret_cast<const float4*>(emb);

    for (int kc = 0; kc < DD / BK; kc++) {
        __syncthreads();  // previous chunk fully consumed
        // load 64x64 chunks of A(rows gi0..) and B(rows gj0..), transposed + swizzled
#pragma unroll
        for (int m = 0; m < 4; m++) {
            int idx = m * 256 + tid;
            int r   = idx >> 4;       // 0..63 (tile row)
            int c4  = idx & 15;       // k-quad within chunk
            int swr = (((r >> 2) ^ c4) << 2) | (r & 3);  // swizzled row slot
            int kl  = c4 * 4;
            float4 va = ev[(size_t)(gi0 + r) * (DD / 4) + kc * (BK / 4) + c4];
            As[(kl + 0) * BM + swr] = va.x;
            As[(kl + 1) * BM + swr] = va.y;
            As[(kl + 2) * BM + swr] = va.z;
            As[(kl + 3) * BM + swr] = va.w;
            float4 vb = ev[(size_t)(gj0 + r) * (DD / 4) + kc * (BK / 4) + c4];
            Bs[(kl + 0) * BM + swr] = vb.x;
            Bs[(kl + 1) * BM + swr] = vb.y;
            Bs[(kl + 2) * BM + swr] = vb.z;
            Bs[(kl + 3) * BM + swr] = vb.w;
        }
        __syncthreads();

#pragma unroll 16
        for (int k = 0; k < BK; k++) {
            int sq = (k >> 2) & 15;
            float4 av = *reinterpret_cast<const float4*>(&As[k * BM + ((ty ^ sq) << 2)]);
            float4 bv = *reinterpret_cast<const float4*>(&Bs[k * BM + ((tx ^ sq) << 2)]);
            unsigned long long b01 = pk2(bv.x, bv.y);
            unsigned long long b23 = pk2(bv.z, bv.w);
            unsigned long long a0 = pk2(av.x, av.x);
            unsigned long long a1 = pk2(av.y, av.y);
            unsigned long long a2 = pk2(av.z, av.z);
            unsigned long long a3 = pk2(av.w, av.w);
            ffma2(acc[0][0], a0, b01); ffma2(acc[0][1], a0, b23);
            ffma2(acc[1][0], a1, b01); ffma2(acc[1][1], a1, b23);
            ffma2(acc[2][0], a2, b01); ffma2(acc[2][1], a2, b23);
            ffma2(acc[3][0], a3, b01); ffma2(acc[3][1], a3, b23);
        }
    }

    __syncthreads();  // all compute loads done; sh can be overlaid with dist
    float* dist = sh; // dist[64][65]

    float maxsq = 0.f;
#pragma unroll
    for (int ii = 0; ii < 4; ii++) {
        int i = 4 * ty + ii;
        float ni = nI[i];
#pragma unroll
        for (int p = 0; p < 2; p++) {
            float dlo, dhi;
            unpk2(acc[ii][p], dlo, dhi);
            int j = 4 * tx + 2 * p;
            float s0 = fmaxf(ni + nJ[j]     - 2.f * dlo, 0.f);
            float s1 = fmaxf(ni + nJ[j + 1] - 2.f * dhi, 0.f);
            maxsq = fmaxf(maxsq, fmaxf(s0, s1));
            dist[i * 65 + j]     = sqrtf(s0);
            dist[i * 65 + j + 1] = sqrtf(s1);
        }
    }
    __syncthreads();

    // ---- W passes: read every W element of this block pair exactly once ----
    float sumDW = 0.f, sW = 0.f;
    if (bi == bj) {
#pragma unroll 4
        for (int p = 0; p < 16; p++) {
            int idx = p * 256 + tid;
            int r = idx >> 6, c = idx & 63;
            float w = W[(size_t)(gi0 + r) * NN + gj0 + c];
            sumDW += dist[r * 65 + c] * w;
            sW += w;
        }
    } else {
#pragma unroll 4
        for (int p = 0; p < 16; p++) {
            int idx = p * 256 + tid;
            int r = idx >> 6, c = idx & 63;
            float w1 = W[(size_t)(gi0 + r) * NN + gj0 + c];   // W[I, J]
            sumDW += dist[r * 65 + c] * w1;
            sW += w1;
            float w2 = W[(size_t)(gj0 + r) * NN + gi0 + c];   // W[J, I]
            sumDW += dist[c * 65 + r] * w2;                    // dist symmetric
            sW += w2;
        }
    }

    // ---- block reductions ----
    red[tid] = (double)sumDW;
    redf[tid] = maxsq;
    __syncthreads();
    for (int s = 128; s > 0; s >>= 1) {
        if (tid < s) {
            red[tid] += red[tid + s];
            redf[tid] = fmaxf(redf[tid], redf[tid + s]);
        }
        __syncthreads();
    }
    if (tid == 0) {
        atomicAdd(&g_sumDW, red[0]);
        atomicMax(&g_maxSq, __float_as_int(redf[0]));
    }
    __syncthreads();
    red[tid] = (double)sW;
    __syncthreads();
    for (int s = 128; s > 0; s >>= 1) {
        if (tid < s) red[tid] += red[tid + s];
        __syncthreads();
    }
    if (tid == 0) atomicAdd(&g_sumW, red[0]);
}

// ---------- kernel 3: finalize ----------
__global__ void finalize_kernel(float* out) {
    double maxd = sqrt((double)__int_as_float(g_maxSq));
    double res = (g_sumW - g_sumDW / maxd) / ((double)NN * (double)NN);
    out[0] = (float)res;
}

extern "C" void kernel_launch(void* const* d_in, const int* in_sizes, int n_in,
                              void* d_out, int out_size) {
    const float* emb = (const float*)d_in[0];   // [8192, 128]
    const float* W   = (const float*)d_in[1];   // [8192, 8192]
    float* out = (float*)d_out;

    init_kernel<<<1, 1>>>();
    norm_kernel<<<NN / 256, 256>>>(emb);
    dim3 grid(NBLK, NBLK);
    main_kernel<<<grid, 256>>>(emb, W);
    finalize_kernel<<<1, 1>>>(out);
}

// round 3
// speedup vs baseline: 1.9608x; 1.9608x over previous
#include <cuda_runtime.h>
#include <cuda_bf16.h>
#include <cstdint>
#include <math.h>

#define NN 8192
#define DD 128
#define TILE 128
#define NB (NN / TILE)          // 64 block-rows
#define NTRI (NB * (NB + 1) / 2) // 2080 triangular tiles

#define LDT 272                  // smem tile row stride in bytes (17*16)
#define TILE_BYTES (TILE * LDT)  // 34816 per matrix
#define OFF_A 0
#define OFF_B TILE_BYTES
#define SMEM_DYN (2 * TILE_BYTES)   // 69632; dist overlay 128*129*4=66048 fits

__device__ double g_sumDW;
__device__ double g_sumW;
__device__ int    g_maxSq;      // float bits; all values >= 0 so int-max works
__device__ float  g_norms[NN];
__device__ __nv_bfloat16 g_ehi[NN * DD];
__device__ __nv_bfloat16 g_elo[NN * DD];

// ---------------- helpers ----------------
__device__ __forceinline__ uint32_t smem_u32(const void* p) {
    uint32_t a;
    asm("{ .reg .u64 t; cvta.to.shared.u64 t, %1; cvt.u32.u64 %0, t; }"
        : "=r"(a) : "l"(p));
    return a;
}
__device__ __forceinline__ void ldsm_x4(uint32_t& r0, uint32_t& r1,
                                        uint32_t& r2, uint32_t& r3, uint32_t a) {
    asm volatile("ldmatrix.sync.aligned.m8n8.x4.shared.b16 {%0,%1,%2,%3}, [%4];"
                 : "=r"(r0), "=r"(r1), "=r"(r2), "=r"(r3) : "r"(a));
}
__device__ __forceinline__ void mma16816(float* d, const uint32_t* a,
                                         const uint32_t* b) {
    asm volatile(
        "mma.sync.aligned.m16n8k16.row.col.f32.bf16.bf16.f32 "
        "{%0,%1,%2,%3}, {%4,%5,%6,%7}, {%8,%9}, {%0,%1,%2,%3};"
        : "+f"(d[0]), "+f"(d[1]), "+f"(d[2]), "+f"(d[3])
        : "r"(a[0]), "r"(a[1]), "r"(a[2]), "r"(a[3]), "r"(b[0]), "r"(b[1]));
}

// ---------------- prep kernels ----------------
__global__ void init_kernel() {
    g_sumDW = 0.0;
    g_sumW  = 0.0;
    g_maxSq = 0;
}

__global__ __launch_bounds__(256) void convert_kernel(const float* __restrict__ emb) {
    int idx = blockIdx.x * 256 + threadIdx.x;
    float x = emb[idx];
    __nv_bfloat16 hi = __float2bfloat16(x);
    g_ehi[idx] = hi;
    g_elo[idx] = __float2bfloat16(x - __bfloat162float(hi));
}

__global__ __launch_bounds__(256) void norm_kernel(const float* __restrict__ emb) {
    int row = blockIdx.x * 256 + threadIdx.x;
    const float4* p = reinterpret_cast<const float4*>(emb) + (size_t)row * (DD / 4);
    float s = 0.f;
#pragma unroll
    for (int i = 0; i < DD / 4; i++) {
        float4 v = p[i];
        s += v.x * v.x + v.y * v.y + v.z * v.z + v.w * v.w;
    }
    g_norms[row] = s;
}

// ---------------- main kernel ----------------
__global__ __launch_bounds__(256, 2) void main_kernel(const float* __restrict__ W) {
    extern __shared__ char sm[];
    __shared__ float nI[TILE];
    __shared__ float nJ[TILE];
    __shared__ float redDW[8], redW[8], redM[8];

    const int tid = threadIdx.x;
    const int wid = tid >> 5;
    const int lane = tid & 31;

    // ---- triangular tile decode: bi <= bj ----
    int t = blockIdx.x;
    float ff = 2.0f * NB + 1.0f;
    int bi = (int)((ff - sqrtf(ff * ff - 8.0f * (float)t)) * 0.5f);
    if (bi < 0) bi = 0;
    if (bi > NB - 1) bi = NB - 1;
    // S(b) = b*NB - b*(b-1)/2
#define SFUN(b) ((b) * NB - (b) * ((b) - 1) / 2)
    while (bi > 0 && SFUN(bi) > t) bi--;
    while (SFUN(bi + 1) <= t) bi++;
    const int bj = bi + (t - SFUN(bi));
    const int gi0 = bi * TILE;
    const int gj0 = bj * TILE;

    if (tid < TILE) nI[tid] = g_norms[gi0 + tid];
    else            nJ[tid - TILE] = g_norms[gj0 + tid - TILE];

    // ---- GEMM: K=256 as two 128-chunks (hi then lo) ----
    const int wm = wid & 3;            // warp row: 32 rows
    const int wn = wid >> 2;           // warp col: 64 cols
    float acc[2][8][4];
#pragma unroll
    for (int mi = 0; mi < 2; mi++)
#pragma unroll
        for (int ni = 0; ni < 8; ni++)
#pragma unroll
            for (int q = 0; q < 4; q++) acc[mi][ni][q] = 0.f;

    const uint32_t smA = smem_u32(sm) + OFF_A;
    const uint32_t smB = smem_u32(sm) + OFF_B;
    // per-lane ldmatrix addresses (byte offsets within a tile)
    const uint32_t a_row = (lane & 15);
    const uint32_t a_koff = ((lane >> 4) << 3) * 2;            // bf16 -> bytes
    const uint32_t b_row = (lane & 7) + ((lane >> 4) << 3);
    const uint32_t b_koff = (((lane >> 3) & 1) << 3) * 2;

    for (int kc = 0; kc < 2; kc++) {
        const uint4* src = (const uint4*)(kc ? g_elo : g_ehi);
        if (kc) __syncthreads();       // previous chunk fully consumed
        // load A (rows gi0..gi0+127) and B (rows gj0..) 128x128 bf16, padded rows
#pragma unroll
        for (int it = 0; it < 8; it++) {
            int idx = it * 256 + tid;
            int r = idx >> 4, c = idx & 15;                    // c: 16B chunk
            *(uint4*)(sm + OFF_A + r * LDT + c * 16) = src[(size_t)(gi0 + r) * 16 + c];
            *(uint4*)(sm + OFF_B + r * LDT + c * 16) = src[(size_t)(gj0 + r) * 16 + c];
        }
        __syncthreads();

#pragma unroll
        for (int ks = 0; ks < 8; ks++) {
            const uint32_t k0b = ks * 32;                      // 16 bf16 = 32 B
            uint32_t af[2][4];
#pragma unroll
            for (int mi = 0; mi < 2; mi++) {
                uint32_t addr = smA + (wm * 32 + mi * 16 + a_row) * LDT + k0b + a_koff;
                ldsm_x4(af[mi][0], af[mi][1], af[mi][2], af[mi][3], addr);
            }
            uint32_t bf[8][2];
#pragma unroll
            for (int nq = 0; nq < 4; nq++) {
                uint32_t addr = smB + (wn * 64 + nq * 16 + b_row) * LDT + k0b + b_koff;
                uint32_t r0, r1, r2, r3;
                ldsm_x4(r0, r1, r2, r3, addr);
                bf[nq * 2][0] = r0; bf[nq * 2][1] = r1;
                bf[nq * 2 + 1][0] = r2; bf[nq * 2 + 1][1] = r3;
            }
#pragma unroll
            for (int mi = 0; mi < 2; mi++)
#pragma unroll
                for (int ni = 0; ni < 8; ni++)
                    mma16816(acc[mi][ni], af[mi], bf[ni]);
        }
    }

    __syncthreads();                   // tiles consumed; overlay dist
    float* dist = (float*)sm;          // [128][129]

    float maxsq = 0.f;
    const int crow = lane >> 2;
    const int ccol = (lane & 3) * 2;
#pragma unroll
    for (int mi = 0; mi < 2; mi++) {
#pragma unroll
        for (int ni = 0; ni < 8; ni++) {
#pragma unroll
            for (int h = 0; h < 2; h++) {                      // c01 / c23 half
                int r = wm * 32 + mi * 16 + crow + h * 8;
                int c = wn * 64 + ni * 8 + ccol;
                float ni_ = nI[r];
                float s0 = fmaxf(ni_ + nJ[c]     - 2.f * acc[mi][ni][2 * h],     0.f);
                float s1 = fmaxf(ni_ + nJ[c + 1] - 2.f * acc[mi][ni][2 * h + 1], 0.f);
                maxsq = fmaxf(maxsq, fmaxf(s0, s1));
                dist[r * 129 + c]     = sqrtf(s0);
                dist[r * 129 + c + 1] = sqrtf(s1);
            }
        }
    }
    __syncthreads();

    // ---- W streaming: every element of this CTA's W block(s) exactly once ----
    const int c = tid & 127;
    const int r0 = tid >> 7;           // 0 or 1; rows r0, r0+2, ..., r0+126
    float sDW = 0.f, sW = 0.f;
    if (bi == bj) {
#pragma unroll 8
        for (int p = 0; p < 64; p++) {
            int r = r0 + 2 * p;
            float w = W[(size_t)(gi0 + r) * NN + gj0 + c];
            sDW += dist[r * 129 + c] * w;
            sW += w;
        }
    } else {
#pragma unroll 8
        for (int p = 0; p < 64; p++) {
            int r = r0 + 2 * p;
            float w1 = W[(size_t)(gi0 + r) * NN + gj0 + c];    // W[I,J]
            float w2 = W[(size_t)(gj0 + r) * NN + gi0 + c];    // W[J,I]
            sDW += dist[r * 129 + c] * w1;
            sDW += dist[c * 129 + r] * w2;                     // dist symmetric
            sW += w1 + w2;
        }
    }

    // ---- reductions ----
#pragma unroll
    for (int o = 16; o > 0; o >>= 1) {
        sDW += __shfl_xor_sync(0xFFFFFFFF, sDW, o);
        sW  += __shfl_xor_sync(0xFFFFFFFF, sW, o);
        maxsq = fmaxf(maxsq, __shfl_xor_sync(0xFFFFFFFF, maxsq, o));
    }
    if (lane == 0) { redDW[wid] = sDW; redW[wid] = sW; redM[wid] = maxsq; }
    __syncthreads();
    if (tid == 0) {
        double a = 0.0, b = 0.0;
        float m = 0.f;
#pragma unroll
        for (int w = 0; w < 8; w++) {
            a += (double)redDW[w];
            b += (double)redW[w];
            m = fmaxf(m, redM[w]);
        }
        atomicAdd(&g_sumDW, a);
        atomicAdd(&g_sumW, b);
        atomicMax(&g_maxSq, __float_as_int(m));
    }
}

// ---------------- finalize ----------------
__global__ void finalize_kernel(float* out) {
    double maxd = sqrt((double)__int_as_float(g_maxSq));
    double res = (g_sumW - g_sumDW / maxd) / ((double)NN * (double)NN);
    out[0] = (float)res;
}

extern "C" void kernel_launch(void* const* d_in, const int* in_sizes, int n_in,
                              void* d_out, int out_size) {
    const float* emb = (const float*)d_in[0];   // [8192, 128] fp32
    const float* W   = (const float*)d_in[1];   // [8192, 8192] fp32
    float* out = (float*)d_out;

    cudaFuncSetAttribute(main_kernel, cudaFuncAttributeMaxDynamicSharedMemorySize,
                         SMEM_DYN);

    init_kernel<<<1, 1>>>();
    convert_kernel<<<(NN * DD) / 256, 256>>>(emb);
    norm_kernel<<<NN / 256, 256>>>(emb);
    main_kernel<<<NTRI, 256, SMEM_DYN>>>(W);
    finalize_kernel<<<1, 1>>>(out);
}